// round 2
// baseline (speedup 1.0000x reference)
#include <cuda_runtime.h>
#include <cstdint>

#define BATCH 16384
#define NB 8
#define BIN 512
#define BOUT 512
#define ROWSTRIDE (NB * BIN)   // 4096

#define BM 128
#define BN 64
#define BK 32
#define THREADS 256

__device__ __forceinline__ uint32_t f2tf32(float f) {
    uint32_t r;
    asm("cvt.rna.tf32.f32 %0, %1;" : "=r"(r) : "f"(f));
    return r;
}

__device__ __forceinline__ void mma_tf32(float* c, const uint32_t* a, const uint32_t* b) {
    asm volatile(
        "mma.sync.aligned.m16n8k8.row.col.f32.tf32.tf32.f32 "
        "{%0,%1,%2,%3}, {%4,%5,%6,%7}, {%8,%9}, {%0,%1,%2,%3};"
        : "+f"(c[0]), "+f"(c[1]), "+f"(c[2]), "+f"(c[3])
        : "r"(a[0]), "r"(a[1]), "r"(a[2]), "r"(a[3]),
          "r"(b[0]), "r"(b[1]));
}

__global__ void __launch_bounds__(THREADS)
block_linear_tf32_kernel(const float* __restrict__ x,
                         const float* __restrict__ W,
                         const float* __restrict__ bias,
                         float* __restrict__ out)
{
    // Padded smem (stride 33) to reduce bank conflicts on fragment reads.
    __shared__ uint32_t As[BM][BK + 1];   // [m][k], tf32 bits
    __shared__ uint32_t Bs[BN][BK + 1];   // [n][k], tf32 bits (W is [out,in] = B^T row-major)

    const int g  = blockIdx.z;            // block (group) index
    const int m0 = blockIdx.x * BM;       // batch-row tile
    const int n0 = blockIdx.y * BN;       // output-feature tile within group

    const int tid  = threadIdx.x;
    const int warp = tid >> 5;
    const int lane = tid & 31;
    const int grp  = lane >> 2;           // 0..7
    const int tig  = lane & 3;            // 0..3

    const int wm = (warp & 3) * 32;       // warp m-offset (4 warps over M)
    const int wn = (warp >> 2) * 32;      // warp n-offset (2 warps over N)

    float acc[2][4][4];
    #pragma unroll
    for (int i = 0; i < 2; i++)
        #pragma unroll
        for (int j = 0; j < 4; j++)
            #pragma unroll
            for (int c = 0; c < 4; c++) acc[i][j][c] = 0.0f;

    const float* xg = x + (size_t)m0 * ROWSTRIDE + (size_t)g * BIN;
    const float* Wg = W + (size_t)g * BOUT * BIN + (size_t)n0 * BIN;

    for (int kt = 0; kt < BIN; kt += BK) {
        // --- load A tile: 128 x 32 fp32, coalesced float4, convert to tf32 ---
        #pragma unroll
        for (int it = 0; it < (BM * BK / 4) / THREADS; it++) {
            int i   = tid + it * THREADS;          // 0..1023
            int row = i >> 3;                      // 8 float4 per 32-wide row
            int k4  = (i & 7) * 4;
            float4 v = *reinterpret_cast<const float4*>(
                xg + (size_t)row * ROWSTRIDE + kt + k4);
            As[row][k4 + 0] = f2tf32(v.x);
            As[row][k4 + 1] = f2tf32(v.y);
            As[row][k4 + 2] = f2tf32(v.z);
            As[row][k4 + 3] = f2tf32(v.w);
        }
        // --- load B tile: 64 x 32 fp32 (W[o][i]) ---
        #pragma unroll
        for (int it = 0; it < (BN * BK / 4) / THREADS; it++) {
            int i   = tid + it * THREADS;          // 0..511
            int row = i >> 3;
            int k4  = (i & 7) * 4;
            float4 v = *reinterpret_cast<const float4*>(
                Wg + (size_t)row * BIN + kt + k4);
            Bs[row][k4 + 0] = f2tf32(v.x);
            Bs[row][k4 + 1] = f2tf32(v.y);
            Bs[row][k4 + 2] = f2tf32(v.z);
            Bs[row][k4 + 3] = f2tf32(v.w);
        }
        __syncthreads();

        #pragma unroll
        for (int ks = 0; ks < BK; ks += 8) {
            uint32_t a[2][4];
            uint32_t bf[4][2];
            #pragma unroll
            for (int mf = 0; mf < 2; mf++) {
                int r = wm + mf * 16;
                a[mf][0] = As[r + grp    ][ks + tig    ];
                a[mf][1] = As[r + grp + 8][ks + tig    ];
                a[mf][2] = As[r + grp    ][ks + tig + 4];
                a[mf][3] = As[r + grp + 8][ks + tig + 4];
            }
            #pragma unroll
            for (int nf = 0; nf < 4; nf++) {
                int c = wn + nf * 8 + grp;
                bf[nf][0] = Bs[c][ks + tig    ];
                bf[nf][1] = Bs[c][ks + tig + 4];
            }
            #pragma unroll
            for (int mf = 0; mf < 2; mf++)
                #pragma unroll
                for (int nf = 0; nf < 4; nf++)
                    mma_tf32(acc[mf][nf], a[mf], bf[nf]);
        }
        __syncthreads();
    }

    // --- epilogue: bias add + store (float2, c0/c1 contiguous columns) ---
    #pragma unroll
    for (int mf = 0; mf < 2; mf++) {
        #pragma unroll
        for (int nf = 0; nf < 4; nf++) {
            int col = n0 + wn + nf * 8 + tig * 2;          // within group, 0..511
            float bv0 = bias[g * BOUT + col];
            float bv1 = bias[g * BOUT + col + 1];
            int r0 = m0 + wm + mf * 16 + grp;
            float* p0 = out + (size_t)r0 * (NB * BOUT) + (size_t)g * BOUT + col;
            float* p1 = p0 + (size_t)8 * (NB * BOUT);
            float2 v0 = make_float2(acc[mf][nf][0] + bv0, acc[mf][nf][1] + bv1);
            float2 v1 = make_float2(acc[mf][nf][2] + bv0, acc[mf][nf][3] + bv1);
            *reinterpret_cast<float2*>(p0) = v0;
            *reinterpret_cast<float2*>(p1) = v1;
        }
    }
}

extern "C" void kernel_launch(void* const* d_in, const int* in_sizes, int n_in,
                              void* d_out, int out_size)
{
    const float* x = (const float*)d_in[0];
    const float* W = (const float*)d_in[1];
    const float* b = (const float*)d_in[2];
    float* out     = (float*)d_out;

    dim3 grid(BATCH / BM, BOUT / BN, NB);   // (128, 8, 8)
    block_linear_tf32_kernel<<<grid, THREADS>>>(x, W, b, out);
}

// round 6
// speedup vs baseline: 2.6991x; 2.6991x over previous
#include <cuda_runtime.h>
#include <cstdint>

#define BATCH 16384
#define NB 8
#define BIN 512
#define BOUT 512
#define ROWSTRIDE 4096

#define BM 128
#define BN 128
#define BK 32
#define STAGES 3
#define THREADS 256
#define KITERS (BIN / BK)          // 16

#define A_STAGE_BYTES (BM * BK * 4)   // 16384
#define B_STAGE_BYTES (BN * BK * 4)   // 16384
#define SMEM_BYTES ((A_STAGE_BYTES + B_STAGE_BYTES) * STAGES)  // 98304

__device__ __forceinline__ uint32_t swz(uint32_t off) {
    // 128B-row xor swizzle: 16B chunk index ^= (row & 7)
    return off ^ ((off >> 3) & 0x70);
}

__device__ __forceinline__ uint32_t f2tf32(uint32_t bits) {
    uint32_t r;
    asm("cvt.rna.tf32.f32 %0, %1;" : "=r"(r) : "f"(__uint_as_float(bits)));
    return r;
}

__device__ __forceinline__ void ldsm_x4(uint32_t* r, uint32_t addr) {
    asm volatile("ldmatrix.sync.aligned.m8n8.x4.shared.b16 {%0,%1,%2,%3}, [%4];"
                 : "=r"(r[0]), "=r"(r[1]), "=r"(r[2]), "=r"(r[3]) : "r"(addr));
}

__device__ __forceinline__ void cp16(uint32_t saddr, const void* g) {
    asm volatile("cp.async.cg.shared.global [%0], [%1], 16;" :: "r"(saddr), "l"(g));
}

__device__ __forceinline__ void cp_commit() {
    asm volatile("cp.async.commit_group;" ::: "memory");
}

template <int N>
__device__ __forceinline__ void cp_wait() {
    asm volatile("cp.async.wait_group %0;" :: "n"(N) : "memory");
}

__device__ __forceinline__ void mma_tf32(float* c, const uint32_t* a,
                                         uint32_t b0, uint32_t b1) {
    asm volatile(
        "mma.sync.aligned.m16n8k8.row.col.f32.tf32.tf32.f32 "
        "{%0,%1,%2,%3}, {%4,%5,%6,%7}, {%8,%9}, {%0,%1,%2,%3};"
        : "+f"(c[0]), "+f"(c[1]), "+f"(c[2]), "+f"(c[3])
        : "r"(a[0]), "r"(a[1]), "r"(a[2]), "r"(a[3]), "r"(b0), "r"(b1));
}

__global__ void __launch_bounds__(THREADS)
block_linear_tf32_pipe(const float* __restrict__ x,
                       const float* __restrict__ W,
                       const float* __restrict__ bias,
                       float* __restrict__ out)
{
    extern __shared__ uint8_t smem[];
    const uint32_t smem_u32 = (uint32_t)__cvta_generic_to_shared(smem);
    const uint32_t aBase = smem_u32;
    const uint32_t bBase = smem_u32 + STAGES * A_STAGE_BYTES;

    const int n0 = blockIdx.x * BN;       // n-tile fastest -> L2 x-slice reuse
    const int g  = blockIdx.y;
    const int m0 = blockIdx.z * BM;

    const int tid  = threadIdx.x;
    const int warp = tid >> 5;
    const int lane = tid & 31;
    const int grp  = lane >> 2;
    const int tig  = lane & 3;

    const int wm = (warp & 3) * 32;       // 4 warps over M (32 each)
    const int wn = (warp >> 2) * 64;      // 2 warps over N (64 each)

    // ldmatrix per-lane addressing pieces
    const int lrow   = lane & 15;         // row within 16-row tile pair
    const int lchunk = (lane >> 4) * 16;  // 0 or 16 bytes (k 0-3 vs 4-7)

    const float* xg = x + (size_t)m0 * ROWSTRIDE + (size_t)g * BIN;
    const float* Wg = W + (size_t)g * BOUT * BIN + (size_t)n0 * BIN;

    float acc[2][8][4];
    #pragma unroll
    for (int i = 0; i < 2; i++)
        #pragma unroll
        for (int j = 0; j < 8; j++)
            #pragma unroll
            for (int c = 0; c < 4; c++) acc[i][j][c] = 0.0f;

    // ---- async load of one stage ----
    auto load_stage = [&](int s, int ki) {
        const float* xk = xg + ki * BK;
        const float* wk = Wg + ki * BK;
        uint32_t aS = aBase + s * A_STAGE_BYTES;
        uint32_t bS = bBase + s * B_STAGE_BYTES;
        #pragma unroll
        for (int it = 0; it < (BM * 8) / THREADS; it++) {   // 128 rows x 8 chunks
            int id  = tid + it * THREADS;
            int row = id >> 3;
            int ch  = id & 7;
            cp16(aS + swz(row * 128 + ch * 16),
                 xk + (size_t)row * ROWSTRIDE + ch * 4);
        }
        #pragma unroll
        for (int it = 0; it < (BN * 8) / THREADS; it++) {
            int id  = tid + it * THREADS;
            int row = id >> 3;
            int ch  = id & 7;
            cp16(bS + swz(row * 128 + ch * 16),
                 wk + (size_t)row * BIN + ch * 4);
        }
    };

    // ---- prologue: fill STAGES-1 stages ----
    #pragma unroll
    for (int s = 0; s < STAGES - 1; s++) {
        load_stage(s, s);
        cp_commit();
    }

    for (int ki = 0; ki < KITERS; ki++) {
        cp_wait<STAGES - 2>();
        __syncthreads();

        const int st = ki % STAGES;
        const uint32_t aS = aBase + st * A_STAGE_BYTES;
        const uint32_t bS = bBase + st * B_STAGE_BYTES;

        #pragma unroll
        for (int ks = 0; ks < BK; ks += 8) {
            uint32_t a[2][4], b[4][4];
            #pragma unroll
            for (int mf = 0; mf < 2; mf++)
                ldsm_x4(a[mf], aS + swz((uint32_t)(wm + mf * 16 + lrow) * 128
                                        + ks * 4 + lchunk));
            #pragma unroll
            for (int q = 0; q < 4; q++)
                ldsm_x4(b[q], bS + swz((uint32_t)(wn + q * 16 + lrow) * 128
                                       + ks * 4 + lchunk));
            #pragma unroll
            for (int mf = 0; mf < 2; mf++)
                #pragma unroll
                for (int j = 0; j < 4; j++) a[mf][j] = f2tf32(a[mf][j]);
            #pragma unroll
            for (int q = 0; q < 4; q++)
                #pragma unroll
                for (int j = 0; j < 4; j++) b[q][j] = f2tf32(b[q][j]);

            #pragma unroll
            for (int mf = 0; mf < 2; mf++) {
                #pragma unroll
                for (int q = 0; q < 4; q++) {
                    mma_tf32(acc[mf][2 * q],     a[mf], b[q][0], b[q][2]);
                    mma_tf32(acc[mf][2 * q + 1], a[mf], b[q][1], b[q][3]);
                }
            }
        }

        int kload = ki + STAGES - 1;
        if (kload < KITERS) load_stage(kload % STAGES, kload);
        cp_commit();
    }

    // ---- epilogue: bias add + store ----
    #pragma unroll
    for (int mf = 0; mf < 2; mf++) {
        #pragma unroll
        for (int nf = 0; nf < 8; nf++) {
            int col = n0 + wn + nf * 8 + tig * 2;           // 0..511 within group
            float bv0 = bias[g * BOUT + col];
            float bv1 = bias[g * BOUT + col + 1];
            int r0 = m0 + wm + mf * 16 + grp;
            float* p0 = out + (size_t)r0 * (NB * BOUT) + (size_t)g * BOUT + col;
            float* p1 = p0 + (size_t)8 * (NB * BOUT);
            float2 v0 = make_float2(acc[mf][nf][0] + bv0, acc[mf][nf][1] + bv1);
            float2 v1 = make_float2(acc[mf][nf][2] + bv0, acc[mf][nf][3] + bv1);
            *reinterpret_cast<float2*>(p0) = v0;
            *reinterpret_cast<float2*>(p1) = v1;
        }
    }
}

extern "C" void kernel_launch(void* const* d_in, const int* in_sizes, int n_in,
                              void* d_out, int out_size)
{
    const float* x = (const float*)d_in[0];
    const float* W = (const float*)d_in[1];
    const float* b = (const float*)d_in[2];
    float* out     = (float*)d_out;

    // Unconditional (no static guards — harness determinism rule).
    // cudaFuncSetAttribute is idempotent and not a stream op; capture-safe.
    cudaFuncSetAttribute(block_linear_tf32_pipe,
                         cudaFuncAttributeMaxDynamicSharedMemorySize,
                         SMEM_BYTES);

    dim3 grid(BOUT / BN, NB, BATCH / BM);   // (4, 8, 128), n fastest
    block_linear_tf32_pipe<<<grid, THREADS, SMEM_BYTES>>>(x, W, b, out);
}

// round 8
// speedup vs baseline: 3.2901x; 1.2190x over previous
#include <cuda_runtime.h>
#include <cstdint>

#define BATCH 16384
#define NB 8
#define BIN 512
#define BOUT 512
#define ROWSTRIDE 4096

#define BM 128
#define BN 128
#define BK 32
#define STAGES 3
#define THREADS 256
#define KITERS (BIN / BK)          // 16

#define A_STAGE_BYTES (BM * BK * 4)   // 16384
#define B_STAGE_BYTES (BN * BK * 4)   // 16384
#define SMEM_BYTES ((A_STAGE_BYTES + B_STAGE_BYTES) * STAGES)  // 98304

// W pre-rounded to tf32-RN (fp32 storage) — removes all in-loop cvts for B,
// and keeps accuracy better than double truncation.
__device__ float g_Wtf[NB * BOUT * BIN];

__device__ __forceinline__ uint32_t swz(uint32_t off) {
    // 128B-row xor swizzle: 16B chunk index ^= (row & 7)
    return off ^ ((off >> 3) & 0x70);
}

__device__ __forceinline__ void ldsm_x4(uint32_t* r, uint32_t addr) {
    asm volatile("ldmatrix.sync.aligned.m8n8.x4.shared.b16 {%0,%1,%2,%3}, [%4];"
                 : "=r"(r[0]), "=r"(r[1]), "=r"(r[2]), "=r"(r[3]) : "r"(addr));
}

__device__ __forceinline__ void cp16(uint32_t saddr, const void* g) {
    asm volatile("cp.async.cg.shared.global [%0], [%1], 16;" :: "r"(saddr), "l"(g));
}

__device__ __forceinline__ void cp_commit() {
    asm volatile("cp.async.commit_group;" ::: "memory");
}

template <int N>
__device__ __forceinline__ void cp_wait() {
    asm volatile("cp.async.wait_group %0;" :: "n"(N) : "memory");
}

__device__ __forceinline__ void mma_tf32(float* c, const uint32_t* a,
                                         uint32_t b0, uint32_t b1) {
    asm volatile(
        "mma.sync.aligned.m16n8k8.row.col.f32.tf32.tf32.f32 "
        "{%0,%1,%2,%3}, {%4,%5,%6,%7}, {%8,%9}, {%0,%1,%2,%3};"
        : "+f"(c[0]), "+f"(c[1]), "+f"(c[2]), "+f"(c[3])
        : "r"(a[0]), "r"(a[1]), "r"(a[2]), "r"(a[3]), "r"(b0), "r"(b1));
}

// ---- W pre-rounding: fp32 -> tf32-RN bits (fp32 storage) ----
__global__ void round_w_kernel(const float* __restrict__ W) {
    int i = (blockIdx.x * blockDim.x + threadIdx.x) * 4;
    float4 v = *reinterpret_cast<const float4*>(W + i);
    uint32_t r0, r1, r2, r3;
    asm("cvt.rna.tf32.f32 %0, %1;" : "=r"(r0) : "f"(v.x));
    asm("cvt.rna.tf32.f32 %0, %1;" : "=r"(r1) : "f"(v.y));
    asm("cvt.rna.tf32.f32 %0, %1;" : "=r"(r2) : "f"(v.z));
    asm("cvt.rna.tf32.f32 %0, %1;" : "=r"(r3) : "f"(v.w));
    float4 o = make_float4(__uint_as_float(r0), __uint_as_float(r1),
                           __uint_as_float(r2), __uint_as_float(r3));
    *reinterpret_cast<float4*>(g_Wtf + i) = o;
}

__global__ void __launch_bounds__(THREADS, 2)
block_linear_tf32_pipe(const float* __restrict__ x,
                       const float* __restrict__ bias,
                       float* __restrict__ out)
{
    extern __shared__ uint8_t smem[];
    const uint32_t smem_u32 = (uint32_t)__cvta_generic_to_shared(smem);
    const uint32_t aBase = smem_u32;
    const uint32_t bBase = smem_u32 + STAGES * A_STAGE_BYTES;

    const int n0 = blockIdx.x * BN;       // n-tile fastest -> L2 x-slice reuse
    const int g  = blockIdx.y;
    const int m0 = blockIdx.z * BM;

    const int tid  = threadIdx.x;
    const int warp = tid >> 5;
    const int lane = tid & 31;
    const int grp  = lane >> 2;
    const int tig  = lane & 3;

    const int wm = (warp & 3) * 32;       // 4 warps over M (32 each)
    const int wn = (warp >> 2) * 64;      // 2 warps over N (64 each)

    // ldmatrix per-lane addressing pieces
    const int lrow   = lane & 15;         // row within 16-row tile pair
    const int lchunk = (lane >> 4) * 16;  // 0 or 16 bytes (k 0-3 vs 4-7)

    const float* xg = x     + (size_t)m0 * ROWSTRIDE + (size_t)g * BIN;
    const float* Wg = g_Wtf + (size_t)g * (BOUT * BIN) + (size_t)n0 * BIN;

    float acc[2][8][4];
    #pragma unroll
    for (int i = 0; i < 2; i++)
        #pragma unroll
        for (int j = 0; j < 8; j++)
            #pragma unroll
            for (int c = 0; c < 4; c++) acc[i][j][c] = 0.0f;

    // ---- async load of one stage ----
    auto load_stage = [&](int s, int ki) {
        const float* xk = xg + ki * BK;
        const float* wk = Wg + ki * BK;
        uint32_t aS = aBase + s * A_STAGE_BYTES;
        uint32_t bS = bBase + s * B_STAGE_BYTES;
        #pragma unroll
        for (int it = 0; it < (BM * 8) / THREADS; it++) {   // 128 rows x 8 chunks
            int id  = tid + it * THREADS;
            int row = id >> 3;
            int ch  = id & 7;
            cp16(aS + swz(row * 128 + ch * 16),
                 xk + (size_t)row * ROWSTRIDE + ch * 4);
        }
        #pragma unroll
        for (int it = 0; it < (BN * 8) / THREADS; it++) {
            int id  = tid + it * THREADS;
            int row = id >> 3;
            int ch  = id & 7;
            cp16(bS + swz(row * 128 + ch * 16),
                 wk + (size_t)row * BIN + ch * 4);
        }
    };

    // ---- prologue: fill STAGES-1 stages ----
    #pragma unroll
    for (int s = 0; s < STAGES - 1; s++) {
        load_stage(s, s);
        cp_commit();
    }

    int st = 0;
    int ls = STAGES - 1;
    for (int ki = 0; ki < KITERS; ki++) {
        cp_wait<STAGES - 2>();
        __syncthreads();

        const uint32_t aS = aBase + st * A_STAGE_BYTES;
        const uint32_t bS = bBase + st * B_STAGE_BYTES;

        #pragma unroll
        for (int ks = 0; ks < BK; ks += 8) {
            uint32_t a[2][4], b[4][4];
            #pragma unroll
            for (int mf = 0; mf < 2; mf++)
                ldsm_x4(a[mf], aS + swz((uint32_t)(wm + mf * 16 + lrow) * 128
                                        + ks * 4 + lchunk));
            #pragma unroll
            for (int q = 0; q < 4; q++)
                ldsm_x4(b[q], bS + swz((uint32_t)(wn + q * 16 + lrow) * 128
                                       + ks * 4 + lchunk));
            // NOTE: no cvt — x fed as raw fp32 bits (HW truncates to tf32),
            // W was pre-rounded to tf32-RN by round_w_kernel.
            #pragma unroll
            for (int mf = 0; mf < 2; mf++) {
                #pragma unroll
                for (int q = 0; q < 4; q++) {
                    mma_tf32(acc[mf][2 * q],     a[mf], b[q][0], b[q][2]);
                    mma_tf32(acc[mf][2 * q + 1], a[mf], b[q][1], b[q][3]);
                }
            }
        }

        int kload = ki + STAGES - 1;
        if (kload < KITERS) load_stage(ls, kload);
        cp_commit();

        st = (st == STAGES - 1) ? 0 : st + 1;
        ls = (ls == STAGES - 1) ? 0 : ls + 1;
    }

    // ---- epilogue: bias add + store ----
    #pragma unroll
    for (int mf = 0; mf < 2; mf++) {
        #pragma unroll
        for (int nf = 0; nf < 8; nf++) {
            int col = n0 + wn + nf * 8 + tig * 2;           // 0..511 within group
            float bv0 = bias[g * BOUT + col];
            float bv1 = bias[g * BOUT + col + 1];
            int r0 = m0 + wm + mf * 16 + grp;
            float* p0 = out + (size_t)r0 * (NB * BOUT) + (size_t)g * BOUT + col;
            float* p1 = p0 + (size_t)8 * (NB * BOUT);
            float2 v0 = make_float2(acc[mf][nf][0] + bv0, acc[mf][nf][1] + bv1);
            float2 v1 = make_float2(acc[mf][nf][2] + bv0, acc[mf][nf][3] + bv1);
            *reinterpret_cast<float2*>(p0) = v0;
            *reinterpret_cast<float2*>(p1) = v1;
        }
    }
}

extern "C" void kernel_launch(void* const* d_in, const int* in_sizes, int n_in,
                              void* d_out, int out_size)
{
    const float* x = (const float*)d_in[0];
    const float* W = (const float*)d_in[1];
    const float* b = (const float*)d_in[2];
    float* out     = (float*)d_out;

    cudaFuncSetAttribute(block_linear_tf32_pipe,
                         cudaFuncAttributeMaxDynamicSharedMemorySize,
                         SMEM_BYTES);

    // 1) pre-round W to tf32-RN (8.4 MB, ~3 us)
    round_w_kernel<<<(NB * BOUT * BIN) / (256 * 4), 256>>>(W);

    // 2) block-diagonal GEMM, no in-loop conversions
    dim3 grid(BOUT / BN, NB, BATCH / BM);   // (4, 8, 128), n fastest
    block_linear_tf32_pipe<<<grid, THREADS, SMEM_BYTES>>>(x, b, out);
}